// round 1
// baseline (speedup 1.0000x reference)
#include <cuda_runtime.h>
#include <cstdint>

// Attention fwd: [B=4,H=8,N=2048,d=64] fp32.
// Flash-attention, TF32 mma.sync.m16n8k8, Br=Bc=64, 4 warps/CTA.

#define NSEQ   2048
#define DHEAD  64
#define BQ     64
#define BK     64
#define STRIDE 72   // smem row stride in floats: (8g+t)%32 -> conflict-free B-frag reads

__device__ __forceinline__ unsigned f2tf(float x) {
    unsigned r;
    asm("cvt.rna.tf32.f32 %0, %1;" : "=r"(r) : "f"(x));
    return r;
}

__device__ __forceinline__ float ex2(float x) {
    float y;
    asm("ex2.approx.f32 %0, %1;" : "=f"(y) : "f"(x));
    return y;
}

__device__ __forceinline__ void mma8(float d[4], const unsigned a[4],
                                     unsigned b0, unsigned b1) {
    asm("mma.sync.aligned.m16n8k8.row.col.f32.tf32.tf32.f32 "
        "{%0,%1,%2,%3},{%4,%5,%6,%7},{%8,%9},{%0,%1,%2,%3};\n"
        : "+f"(d[0]), "+f"(d[1]), "+f"(d[2]), "+f"(d[3])
        : "r"(a[0]), "r"(a[1]), "r"(a[2]), "r"(a[3]), "r"(b0), "r"(b1));
}

__global__ void __launch_bounds__(128)
fa_tf32_kernel(const float* __restrict__ Q, const float* __restrict__ K,
               const float* __restrict__ V, float* __restrict__ O) {
    extern __shared__ float sm[];
    float* sK = sm;                      // [BK][STRIDE]   K tile, tf32 bits
    float* sV = sm + BK * STRIDE;        // [BK][STRIDE]   V tile (key-major), tf32 bits
    float* sP = sm + 2 * BK * STRIDE;    // [4*16][STRIDE] per-warp P tiles, tf32 bits

    const int tid  = threadIdx.x;
    const int w    = tid >> 5;
    const int lane = tid & 31;
    const int g    = lane >> 2;   // group id (row within 8)
    const int t    = lane & 3;    // thread in group

    const int qtile = blockIdx.x;
    const int bh    = blockIdx.y;
    const size_t base = (size_t)bh * NSEQ * DHEAD;

    const float scale = 0.125f;  // 1/sqrt(64)
    const float L2E   = 1.4426950408889634f;

    // ---- Q fragments resident in registers (scale folded in) ----
    unsigned qa[8][4];
    {
        const float* q0 = Q + base + (size_t)(qtile * BQ + w * 16 + g) * DHEAD;
        const float* q1 = q0 + 8 * DHEAD;
#pragma unroll
        for (int kc = 0; kc < 8; kc++) {
            qa[kc][0] = f2tf(q0[kc * 8 + t]     * scale);
            qa[kc][1] = f2tf(q1[kc * 8 + t]     * scale);
            qa[kc][2] = f2tf(q0[kc * 8 + t + 4] * scale);
            qa[kc][3] = f2tf(q1[kc * 8 + t + 4] * scale);
        }
    }

    float acc[8][4];
#pragma unroll
    for (int i = 0; i < 8; i++)
#pragma unroll
        for (int c = 0; c < 4; c++) acc[i][c] = 0.f;

    float m0 = -1e30f, m1 = -1e30f, l0 = 0.f, l1 = 0.f;

    float* sPw = sP + w * 16 * STRIDE;

    for (int j = 0; j < NSEQ / BK; j++) {
        __syncthreads();  // previous iter's smem reads complete
        // ---- stage K, V tile (convert to tf32 at store) ----
        {
            const float4* Kg = (const float4*)(K + base + (size_t)j * BK * DHEAD);
            const float4* Vg = (const float4*)(V + base + (size_t)j * BK * DHEAD);
#pragma unroll
            for (int i = 0; i < 8; i++) {
                int idx = i * 128 + tid;          // 1024 float4 total
                int r   = idx >> 4;
                int c4  = (idx & 15) * 4;
                float4 kv = Kg[idx];
                sK[r * STRIDE + c4 + 0] = __uint_as_float(f2tf(kv.x));
                sK[r * STRIDE + c4 + 1] = __uint_as_float(f2tf(kv.y));
                sK[r * STRIDE + c4 + 2] = __uint_as_float(f2tf(kv.z));
                sK[r * STRIDE + c4 + 3] = __uint_as_float(f2tf(kv.w));
                float4 vv = Vg[idx];
                sV[r * STRIDE + c4 + 0] = __uint_as_float(f2tf(vv.x));
                sV[r * STRIDE + c4 + 1] = __uint_as_float(f2tf(vv.y));
                sV[r * STRIDE + c4 + 2] = __uint_as_float(f2tf(vv.z));
                sV[r * STRIDE + c4 + 3] = __uint_as_float(f2tf(vv.w));
            }
        }
        __syncthreads();

        // ---- S = Qs * K^T : per warp 16x64 ----
        float s[8][4];
#pragma unroll
        for (int i = 0; i < 8; i++)
#pragma unroll
            for (int c = 0; c < 4; c++) s[i][c] = 0.f;

#pragma unroll
        for (int kc = 0; kc < 8; kc++) {
#pragma unroll
            for (int nt = 0; nt < 8; nt++) {
                unsigned b0 = __float_as_uint(sK[(nt * 8 + g) * STRIDE + kc * 8 + t]);
                unsigned b1 = __float_as_uint(sK[(nt * 8 + g) * STRIDE + kc * 8 + t + 4]);
                mma8(s[nt], qa[kc], b0, b1);
            }
        }

        // ---- online softmax (rows g and g+8; each row owned by 4 lanes) ----
        float rm0 = -1e30f, rm1 = -1e30f;
#pragma unroll
        for (int nt = 0; nt < 8; nt++) {
            rm0 = fmaxf(rm0, fmaxf(s[nt][0], s[nt][1]));
            rm1 = fmaxf(rm1, fmaxf(s[nt][2], s[nt][3]));
        }
        rm0 = fmaxf(rm0, __shfl_xor_sync(0xffffffffu, rm0, 1));
        rm0 = fmaxf(rm0, __shfl_xor_sync(0xffffffffu, rm0, 2));
        rm1 = fmaxf(rm1, __shfl_xor_sync(0xffffffffu, rm1, 1));
        rm1 = fmaxf(rm1, __shfl_xor_sync(0xffffffffu, rm1, 2));

        float mn0 = fmaxf(m0, rm0), mn1 = fmaxf(m1, rm1);
        float cor0 = ex2((m0 - mn0) * L2E);
        float cor1 = ex2((m1 - mn1) * L2E);
        m0 = mn0; m1 = mn1;

        float rs0 = 0.f, rs1 = 0.f;
#pragma unroll
        for (int nt = 0; nt < 8; nt++) {
            float p0 = ex2((s[nt][0] - mn0) * L2E);
            float p1 = ex2((s[nt][1] - mn0) * L2E);
            float p2 = ex2((s[nt][2] - mn1) * L2E);
            float p3 = ex2((s[nt][3] - mn1) * L2E);
            rs0 += p0 + p1;
            rs1 += p2 + p3;
            sPw[g * STRIDE + nt * 8 + 2 * t]           = __uint_as_float(f2tf(p0));
            sPw[g * STRIDE + nt * 8 + 2 * t + 1]       = __uint_as_float(f2tf(p1));
            sPw[(g + 8) * STRIDE + nt * 8 + 2 * t]     = __uint_as_float(f2tf(p2));
            sPw[(g + 8) * STRIDE + nt * 8 + 2 * t + 1] = __uint_as_float(f2tf(p3));
        }
        rs0 += __shfl_xor_sync(0xffffffffu, rs0, 1);
        rs0 += __shfl_xor_sync(0xffffffffu, rs0, 2);
        rs1 += __shfl_xor_sync(0xffffffffu, rs1, 1);
        rs1 += __shfl_xor_sync(0xffffffffu, rs1, 2);
        l0 = l0 * cor0 + rs0;
        l1 = l1 * cor1 + rs1;

#pragma unroll
        for (int nt = 0; nt < 8; nt++) {
            acc[nt][0] *= cor0;
            acc[nt][1] *= cor0;
            acc[nt][2] *= cor1;
            acc[nt][3] *= cor1;
        }

        __syncwarp();  // sPw write -> read, same warp only

        // ---- O += P * V ----
#pragma unroll
        for (int kc = 0; kc < 8; kc++) {
            unsigned a[4];
            a[0] = __float_as_uint(sPw[g * STRIDE + kc * 8 + t]);
            a[1] = __float_as_uint(sPw[(g + 8) * STRIDE + kc * 8 + t]);
            a[2] = __float_as_uint(sPw[g * STRIDE + kc * 8 + t + 4]);
            a[3] = __float_as_uint(sPw[(g + 8) * STRIDE + kc * 8 + t + 4]);
#pragma unroll
            for (int nt = 0; nt < 8; nt++) {
                unsigned b0 = __float_as_uint(sV[(kc * 8 + t) * STRIDE + nt * 8 + g]);
                unsigned b1 = __float_as_uint(sV[(kc * 8 + t + 4) * STRIDE + nt * 8 + g]);
                mma8(acc[nt], a, b0, b1);
            }
        }
    }

    // ---- epilogue: O = acc / l ----
    float inv0 = __frcp_rn(l0);
    float inv1 = __frcp_rn(l1);
    float* o0 = O + base + (size_t)(qtile * BQ + w * 16 + g) * DHEAD;
    float* o1 = o0 + 8 * DHEAD;
#pragma unroll
    for (int nt = 0; nt < 8; nt++) {
        float2 v0 = make_float2(acc[nt][0] * inv0, acc[nt][1] * inv0);
        float2 v1 = make_float2(acc[nt][2] * inv1, acc[nt][3] * inv1);
        *(float2*)(o0 + nt * 8 + 2 * t) = v0;
        *(float2*)(o1 + nt * 8 + 2 * t) = v1;
    }
}

extern "C" void kernel_launch(void* const* d_in, const int* in_sizes, int n_in,
                              void* d_out, int out_size) {
    const float* Q = (const float*)d_in[0];
    const float* K = (const float*)d_in[1];
    const float* V = (const float*)d_in[2];
    float* O = (float*)d_out;

    const int bh = in_sizes[0] / (NSEQ * DHEAD);  // B*H = 32
    const int smem_bytes = 3 * BK * STRIDE * sizeof(float);  // 55296

    cudaFuncSetAttribute(fa_tf32_kernel,
                         cudaFuncAttributeMaxDynamicSharedMemorySize, smem_bytes);

    dim3 grid(NSEQ / BQ, bh);
    fa_tf32_kernel<<<grid, 128, smem_bytes>>>(Q, K, V, O);
}

// round 3
// speedup vs baseline: 1.2107x; 1.2107x over previous
#include <cuda_runtime.h>
#include <cstdint>

// Attention fwd [B=4,H=8,N=2048,d=64] fp32.
// Flash-attention, legacy mma.sync m16n8k8 TF32.
// BQ=128 (4 warps x 32 q-rows), BK=64, cp.async double-buffered K/V.

#define NSEQ   2048
#define DHEAD  64
#define BQ     128
#define BK     64
#define NITER  (NSEQ / BK)
#define STR    68                 // smem row stride (floats): conflict-free
#define TILEF  (BK * STR)         // floats per K or V tile (4352)
#define TILEB  (TILEF * 4)        // bytes (17408)
#define SMP_F  (4 * TILEF)        // P region start (floats)
#define SM_TOTAL_B ((4 * TILEF + 4 * 32 * STR) * 4)   // 104448 bytes

__device__ __forceinline__ unsigned f2tf(float x) {
    unsigned r;
    asm("cvt.rna.tf32.f32 %0, %1;" : "=r"(r) : "f"(x));
    return r;
}
__device__ __forceinline__ float ex2f(float x) {
    float y;
    asm("ex2.approx.f32 %0, %1;" : "=f"(y) : "f"(x));
    return y;
}
__device__ __forceinline__ uint32_t smem_u32(const void* p) {
    uint32_t a;
    asm("{ .reg .u64 t; cvta.to.shared.u64 t, %1; cvt.u32.u64 %0, t; }" : "=r"(a) : "l"(p));
    return a;
}
__device__ __forceinline__ void cpa16(uint32_t dst, const void* src) {
    asm volatile("cp.async.cg.shared.global [%0], [%1], 16;" :: "r"(dst), "l"(src) : "memory");
}
#define CP_COMMIT() asm volatile("cp.async.commit_group;" ::: "memory")
#define CP_WAIT1()  asm volatile("cp.async.wait_group 1;"  ::: "memory")

__device__ __forceinline__ void mma8(float d[4], const unsigned a[4],
                                     unsigned b0, unsigned b1) {
    asm("mma.sync.aligned.m16n8k8.row.col.f32.tf32.tf32.f32 "
        "{%0,%1,%2,%3},{%4,%5,%6,%7},{%8,%9},{%0,%1,%2,%3};\n"
        : "+f"(d[0]), "+f"(d[1]), "+f"(d[2]), "+f"(d[3])
        : "r"(a[0]), "r"(a[1]), "r"(a[2]), "r"(a[3]), "r"(b0), "r"(b1));
}

__global__ void __launch_bounds__(128, 2)
fa_tf32_v3(const float* __restrict__ Q, const float* __restrict__ K,
           const float* __restrict__ V, float* __restrict__ O) {
    extern __shared__ float sm[];
    const uint32_t sb = smem_u32(sm);

    const int tid  = threadIdx.x;
    const int w    = tid >> 5;
    const int lane = tid & 31;
    const int g    = lane >> 2;
    const int t    = lane & 3;

    const int qtile = blockIdx.x;
    const int bh    = blockIdx.y;
    const size_t base = (size_t)bh * NSEQ * DHEAD;
    const float L2E = 1.4426950408889634f;

    // ---- Q fragments in registers (tf32-rounded, scale folded), 2 row-blocks ----
    unsigned qa[2][8][4];
    {
        const float* Qb = Q + base + (size_t)(qtile * BQ + w * 32) * DHEAD;
#pragma unroll
        for (int b = 0; b < 2; b++) {
            const float* q0 = Qb + (size_t)(16 * b + g) * DHEAD;
            const float* q1 = q0 + 8 * DHEAD;
#pragma unroll
            for (int kc = 0; kc < 8; kc++) {
                qa[b][kc][0] = f2tf(q0[kc * 8 + t]     * 0.125f);
                qa[b][kc][1] = f2tf(q1[kc * 8 + t]     * 0.125f);
                qa[b][kc][2] = f2tf(q0[kc * 8 + t + 4] * 0.125f);
                qa[b][kc][3] = f2tf(q1[kc * 8 + t + 4] * 0.125f);
            }
        }
    }

    // ---- staging helper: cp.async K,V tile j into buffer (j&1) ----
    auto stage = [&](int j) {
        const int buf = j & 1;
        const char* Ks = (const char*)(K + base + (size_t)j * BK * DHEAD);
        const char* Vs = (const char*)(V + base + (size_t)j * BK * DHEAD);
        const uint32_t kb = sb + (buf ? 2u * TILEB : 0u);
#pragma unroll
        for (int i = 0; i < 8; i++) {
            int idx = i * 128 + tid;
            int r = idx >> 4, c = idx & 15;
            cpa16(kb + r * (STR * 4) + c * 16, Ks + r * 256 + c * 16);
            cpa16(kb + TILEB + r * (STR * 4) + c * 16, Vs + r * 256 + c * 16);
        }
    };

    stage(0); CP_COMMIT();
    stage(1); CP_COMMIT();

    float acc[2][8][4];
#pragma unroll
    for (int b = 0; b < 2; b++)
#pragma unroll
        for (int nt = 0; nt < 8; nt++)
#pragma unroll
            for (int c = 0; c < 4; c++) acc[b][nt][c] = 0.f;

    float m[4] = {-1e30f, -1e30f, -1e30f, -1e30f};
    float l[4] = {0.f, 0.f, 0.f, 0.f};

    float* sPw = sm + SMP_F + w * (32 * STR);

    for (int j = 0; j < NITER; j++) {
        CP_WAIT1();
        __syncthreads();

        const float* kb = sm + ((j & 1) ? 2 * TILEF : 0);
        const float* vb = kb + TILEF;

        // ---- S = Q K^T : 2 row-blocks share each B fragment ----
        float s[2][8][4];
#pragma unroll
        for (int b = 0; b < 2; b++)
#pragma unroll
            for (int nt = 0; nt < 8; nt++)
#pragma unroll
                for (int c = 0; c < 4; c++) s[b][nt][c] = 0.f;

#pragma unroll
        for (int kc = 0; kc < 8; kc++) {
#pragma unroll
            for (int nt = 0; nt < 8; nt++) {
                unsigned b0 = __float_as_uint(kb[(nt * 8 + g) * STR + kc * 8 + t]);
                unsigned b1 = __float_as_uint(kb[(nt * 8 + g) * STR + kc * 8 + t + 4]);
                mma8(s[0][nt], qa[0][kc], b0, b1);
                mma8(s[1][nt], qa[1][kc], b0, b1);
            }
        }

        // ---- online softmax: 4 row-groups per thread ----
        float rm[4] = {-1e30f, -1e30f, -1e30f, -1e30f};
#pragma unroll
        for (int b = 0; b < 2; b++)
#pragma unroll
            for (int nt = 0; nt < 8; nt++) {
                rm[2 * b]     = fmaxf(rm[2 * b],     fmaxf(s[b][nt][0], s[b][nt][1]));
                rm[2 * b + 1] = fmaxf(rm[2 * b + 1], fmaxf(s[b][nt][2], s[b][nt][3]));
            }
#pragma unroll
        for (int r = 0; r < 4; r++) {
            rm[r] = fmaxf(rm[r], __shfl_xor_sync(0xffffffffu, rm[r], 1));
            rm[r] = fmaxf(rm[r], __shfl_xor_sync(0xffffffffu, rm[r], 2));
        }
        float mnL[4], cor[4];
#pragma unroll
        for (int r = 0; r < 4; r++) {
            float mn = fmaxf(m[r], rm[r]);
            mnL[r] = mn * L2E;
            cor[r] = ex2f(fmaf(m[r], L2E, -mnL[r]));
            m[r] = mn;
        }
        float rs[4] = {0.f, 0.f, 0.f, 0.f};
#pragma unroll
        for (int b = 0; b < 2; b++)
#pragma unroll
            for (int nt = 0; nt < 8; nt++) {
                float p0 = __uint_as_float(f2tf(ex2f(fmaf(s[b][nt][0], L2E, -mnL[2 * b]))));
                float p1 = __uint_as_float(f2tf(ex2f(fmaf(s[b][nt][1], L2E, -mnL[2 * b]))));
                float p2 = __uint_as_float(f2tf(ex2f(fmaf(s[b][nt][2], L2E, -mnL[2 * b + 1]))));
                float p3 = __uint_as_float(f2tf(ex2f(fmaf(s[b][nt][3], L2E, -mnL[2 * b + 1]))));
                rs[2 * b]     += p0 + p1;
                rs[2 * b + 1] += p2 + p3;
                s[b][nt][0] = p0; s[b][nt][1] = p1; s[b][nt][2] = p2; s[b][nt][3] = p3;
            }
#pragma unroll
        for (int r = 0; r < 4; r++) {
            rs[r] += __shfl_xor_sync(0xffffffffu, rs[r], 1);
            rs[r] += __shfl_xor_sync(0xffffffffu, rs[r], 2);
            l[r] = l[r] * cor[r] + rs[r];
        }
#pragma unroll
        for (int b = 0; b < 2; b++)
#pragma unroll
            for (int nt = 0; nt < 8; nt++) {
                acc[b][nt][0] *= cor[2 * b];
                acc[b][nt][1] *= cor[2 * b];
                acc[b][nt][2] *= cor[2 * b + 1];
                acc[b][nt][3] *= cor[2 * b + 1];
            }

        // ---- P -> per-warp smem region ----
#pragma unroll
        for (int b = 0; b < 2; b++)
#pragma unroll
            for (int nt = 0; nt < 8; nt++) {
                *(float2*)&sPw[(16 * b + g) * STR + nt * 8 + 2 * t] =
                    make_float2(s[b][nt][0], s[b][nt][1]);
                *(float2*)&sPw[(16 * b + 8 + g) * STR + nt * 8 + 2 * t] =
                    make_float2(s[b][nt][2], s[b][nt][3]);
            }
        __syncwarp();

        // ---- O += P V ----
#pragma unroll
        for (int kc = 0; kc < 8; kc++) {
            unsigned a0[4], a1[4];
            a0[0] = __float_as_uint(sPw[(g)      * STR + kc * 8 + t]);
            a0[1] = __float_as_uint(sPw[(8 + g)  * STR + kc * 8 + t]);
            a0[2] = __float_as_uint(sPw[(g)      * STR + kc * 8 + t + 4]);
            a0[3] = __float_as_uint(sPw[(8 + g)  * STR + kc * 8 + t + 4]);
            a1[0] = __float_as_uint(sPw[(16 + g) * STR + kc * 8 + t]);
            a1[1] = __float_as_uint(sPw[(24 + g) * STR + kc * 8 + t]);
            a1[2] = __float_as_uint(sPw[(16 + g) * STR + kc * 8 + t + 4]);
            a1[3] = __float_as_uint(sPw[(24 + g) * STR + kc * 8 + t + 4]);
#pragma unroll
            for (int nt = 0; nt < 8; nt++) {
                unsigned b0 = __float_as_uint(vb[(kc * 8 + t)     * STR + nt * 8 + g]);
                unsigned b1 = __float_as_uint(vb[(kc * 8 + t + 4) * STR + nt * 8 + g]);
                mma8(acc[0][nt], a0, b0, b1);
                mma8(acc[1][nt], a1, b0, b1);
            }
        }

        __syncthreads();
        if (j + 2 < NITER) stage(j + 2);
        CP_COMMIT();
    }

    // ---- epilogue ----
    float inv[4];
#pragma unroll
    for (int r = 0; r < 4; r++) inv[r] = __frcp_rn(l[r]);

    float* Ob = O + base + (size_t)(qtile * BQ + w * 32) * DHEAD;
#pragma unroll
    for (int b = 0; b < 2; b++)
#pragma unroll
        for (int nt = 0; nt < 8; nt++) {
            *(float2*)&Ob[(size_t)(16 * b + g) * DHEAD + nt * 8 + 2 * t] =
                make_float2(acc[b][nt][0] * inv[2 * b], acc[b][nt][1] * inv[2 * b]);
            *(float2*)&Ob[(size_t)(16 * b + 8 + g) * DHEAD + nt * 8 + 2 * t] =
                make_float2(acc[b][nt][2] * inv[2 * b + 1], acc[b][nt][3] * inv[2 * b + 1]);
        }
}

extern "C" void kernel_launch(void* const* d_in, const int* in_sizes, int n_in,
                              void* d_out, int out_size) {
    const float* Q = (const float*)d_in[0];
    const float* K = (const float*)d_in[1];
    const float* V = (const float*)d_in[2];
    float* O = (float*)d_out;

    const int bh = in_sizes[0] / (NSEQ * DHEAD);  // 32

    cudaFuncSetAttribute(fa_tf32_v3,
                         cudaFuncAttributeMaxDynamicSharedMemorySize, SM_TOTAL_B);

    dim3 grid(NSEQ / BQ, bh);
    fa_tf32_v3<<<grid, 128, SM_TOTAL_B>>>(Q, K, V, O);
}